// round 11
// baseline (speedup 1.0000x reference)
#include <cuda_runtime.h>
#include <cuda_bf16.h>
#include <cstdint>

// ---------------- problem constants ----------------
#define SEQ   512
#define BATCH 64
#define EMB   512
#define HID   1024
#define G4    4096
#define NCTA  128
#define HPC   8
#define CPC   32

// ---------------- device scratch ----------------
__device__ float             d_WfoldT[(size_t)G4 * EMB];                // 8 MB, [n][k] transposed+perm
__device__ float             d_bias2[G4];
__device__ float             d_gates[(size_t)SEQ * NCTA * BATCH * CPC]; // 512 MB [t][cta][b][32]
__device__ float             d_hbuf[2][BATCH * HID];                    // k-permuted storage
__device__ volatile unsigned d_flags[NCTA];

// ---------------- helpers ----------------
__device__ __forceinline__ int p8(int e) { return ((e & 3) << 1) | (e >> 2); }

__device__ __forceinline__ float tf32r(float x) {
    uint32_t u;
    asm("cvt.rna.tf32.f32 %0, %1;" : "=r"(u) : "f"(x));
    return __uint_as_float(u);
}
__device__ __forceinline__ float sigf(float x) { return __fdividef(1.f, 1.f + __expf(-x)); }
__device__ __forceinline__ float tanf_(float x) { return __fdividef(2.f, 1.f + __expf(-2.f * x)) - 1.f; }

__device__ __forceinline__ uint32_t smem_u32(const void* p) {
    uint32_t a;
    asm("{ .reg .u64 t; cvta.to.shared.u64 t, %1; cvt.u32.u64 %0, t; }" : "=r"(a) : "l"(p));
    return a;
}
__device__ __forceinline__ void cp16_sm(uint32_t s, const float* g) {
    asm volatile("cp.async.cg.shared.global [%0], [%1], 16;" :: "r"(s), "l"(g));
}
__device__ __forceinline__ unsigned ld_acq(const unsigned* p) {
    unsigned v;
    asm volatile("ld.acquire.gpu.global.u32 %0, [%1];" : "=r"(v) : "l"(p));
    return v;
}
__device__ __forceinline__ void mma_tf32(float c[4],
                                         uint32_t a0, uint32_t a1, uint32_t a2, uint32_t a3,
                                         uint32_t b0, uint32_t b1) {
    asm volatile(
        "mma.sync.aligned.m16n8k8.row.col.f32.tf32.tf32.f32 "
        "{%0,%1,%2,%3}, {%4,%5,%6,%7}, {%8,%9}, {%0,%1,%2,%3};\n"
        : "+f"(c[0]), "+f"(c[1]), "+f"(c[2]), "+f"(c[3])
        : "r"(a0), "r"(a1), "r"(a2), "r"(a3), "r"(b0), "r"(b1));
}

// ================= K1: fold  WfoldT[n][perm(k)] = (bridge_w @ w_ih)[k][n] =================
__global__ __launch_bounds__(256) void k_fold(const float* __restrict__ bw,
                                              const float* __restrict__ wih) {
    __shared__ float As[64][17];
    __shared__ float Bs[16][68];
    const int tid = threadIdx.x;
    const int n0 = blockIdx.x * 64, m0 = blockIdx.y * 64;
    const int tx = tid & 15, ty = tid >> 4;
    const int ar = tid >> 2, ac4 = (tid & 3) * 4;
    const int br = tid >> 4, bc4 = (tid & 15) * 4;

    float acc[4][4] = {};
    for (int kc = 0; kc < 512; kc += 16) {
        float4 av = *(const float4*)(bw + (size_t)(m0 + ar) * 512 + kc + ac4);
        As[ar][ac4 + 0] = av.x; As[ar][ac4 + 1] = av.y;
        As[ar][ac4 + 2] = av.z; As[ar][ac4 + 3] = av.w;
        float4 bv = *(const float4*)(wih + (size_t)(kc + br) * G4 + n0 + bc4);
        Bs[br][bc4 + 0] = bv.x; Bs[br][bc4 + 1] = bv.y;
        Bs[br][bc4 + 2] = bv.z; Bs[br][bc4 + 3] = bv.w;
        __syncthreads();
#pragma unroll
        for (int k = 0; k < 16; k++) {
            float a[4], b[4];
#pragma unroll
            for (int i = 0; i < 4; i++) a[i] = As[ty * 4 + i][k];
#pragma unroll
            for (int j = 0; j < 4; j++) b[j] = Bs[k][tx * 4 + j];
#pragma unroll
            for (int i = 0; i < 4; i++)
#pragma unroll
                for (int j = 0; j < 4; j++) acc[i][j] += a[i] * b[j];
        }
        __syncthreads();
    }
#pragma unroll
    for (int i = 0; i < 4; i++) {
        const int m = m0 + ty * 4 + i;
        const int mp = (m & ~7) | p8(m & 7);
#pragma unroll
        for (int j = 0; j < 4; j++)
            d_WfoldT[(size_t)(n0 + tx * 4 + j) * 512 + mp] = tf32r(acc[i][j]);
    }
}

// ================= Kb: bias2 ; reset flags ================
__global__ __launch_bounds__(256) void k_bias(const float* __restrict__ bb,
                                              const float* __restrict__ wih,
                                              const float* __restrict__ bih,
                                              const float* __restrict__ bhh) {
    const int g = blockIdx.x * blockDim.x + threadIdx.x;
    if (g < NCTA) d_flags[g] = 0u;
    if (g >= G4) return;
    float acc = bih[g] + bhh[g];
    for (int e = 0; e < 512; e++) acc += bb[e] * wih[(size_t)e * G4 + g];
    d_bias2[g] = acc;
}

// ================= K2: gates = gather(emb) @ Wfold + bias2 ================
#define AS_STR 36
#define KG_SMEM ((2 * 128 * AS_STR + 2 * 64 * AS_STR + 64) * 4)

__global__ __launch_bounds__(256, 2) void k_gates(const int* __restrict__ x,
                                                  const float* __restrict__ emb) {
    extern __shared__ float sg[];
    float* As = sg;                          // [2][128][36]
    float* Bs = sg + 2 * 128 * AS_STR;       // [2][64][36]
    float* bias_s = Bs + 2 * 64 * AS_STR;    // [64]
    const uint32_t sbB = smem_u32(Bs);

    const int tid  = threadIdx.x;
    const int t0   = blockIdx.y * 2;
    const int n0   = blockIdx.x * 64;
    const int lane = tid & 31, wid = tid >> 5;
    const int gid  = lane >> 2, t4 = lane & 3;
    const int wm   = wid >> 1, wn = wid & 1;

    if (tid < 64) bias_s[tid] = d_bias2[n0 + tid];

    const int r    = tid >> 1, half = tid & 1;
    const int tokb = r & 63, tokt = t0 + (r >> 6);
    const float* arow = emb + (size_t)x[(size_t)tokb * SEQ + tokt] * EMB;

    float4 RA[2][2];
#define LDGA(KB) do { \
    const int _e0 = (KB) * 32 + half * 16; \
    RA[0][0] = *(const float4*)(arow + _e0);      RA[0][1] = *(const float4*)(arow + _e0 + 4); \
    RA[1][0] = *(const float4*)(arow + _e0 + 8);  RA[1][1] = *(const float4*)(arow + _e0 + 12); \
} while (0)
#define STSA(BUF) do { \
    float* _dst = As + (BUF) * 128 * AS_STR + r * AS_STR + half * 16; \
    _Pragma("unroll") for (int _g = 0; _g < 2; _g++) { \
        const float* _f0 = (const float*)&RA[_g][0]; \
        const float* _f1 = (const float*)&RA[_g][1]; \
        _Pragma("unroll") for (int _i = 0; _i < 4; _i++) { \
            float2 _pr; _pr.x = tf32r(_f0[_i]); _pr.y = tf32r(_f1[_i]); \
            *(float2*)(_dst + _g * 8 + 2 * _i) = _pr; \
        } \
    } \
} while (0)
#define CPB(KB, BUF) do { \
    _Pragma("unroll") for (int _i = 0; _i < 2; _i++) { \
        const int _idx = tid + _i * 256; \
        const int _n = _idx >> 3, _f = _idx & 7; \
        cp16_sm(sbB + ((BUF) * 64 * AS_STR + _n * AS_STR + _f * 4) * 4, \
                d_WfoldT + (size_t)(n0 + _n) * 512 + (KB) * 32 + _f * 4); \
    } \
    asm volatile("cp.async.commit_group;" ::: "memory"); \
} while (0)

    float C[2][4][4] = {};

    LDGA(0); CPB(0, 0); STSA(0);
    LDGA(1); CPB(1, 1); STSA(1);
    LDGA(2);

    for (int kb = 0; kb < 16; kb++) {
        if (kb < 15) asm volatile("cp.async.wait_group 1;" ::: "memory");
        else         asm volatile("cp.async.wait_group 0;" ::: "memory");
        __syncthreads();
        {
            const float* Ab = As + (kb & 1) * 128 * AS_STR;
            const float* Bb = Bs + (kb & 1) * 64 * AS_STR;
#pragma unroll
            for (int ks = 0; ks < 4; ks++) {
                float2 au[2], av[2];
#pragma unroll
                for (int mf = 0; mf < 2; mf++) {
                    const int rr = wm * 32 + mf * 16 + gid;
                    au[mf] = *(const float2*)(Ab + rr * AS_STR + ks * 8 + 2 * t4);
                    av[mf] = *(const float2*)(Ab + (rr + 8) * AS_STR + ks * 8 + 2 * t4);
                }
                uint32_t bu[4][2];
#pragma unroll
                for (int nf = 0; nf < 4; nf++) {
                    float2 bv = *(const float2*)(Bb + (wn * 32 + nf * 8 + gid) * AS_STR + ks * 8 + 2 * t4);
                    bu[nf][0] = __float_as_uint(bv.x);
                    bu[nf][1] = __float_as_uint(bv.y);
                }
#pragma unroll
                for (int mf = 0; mf < 2; mf++)
#pragma unroll
                    for (int nf = 0; nf < 4; nf++)
                        mma_tf32(C[mf][nf],
                                 __float_as_uint(au[mf].x), __float_as_uint(av[mf].x),
                                 __float_as_uint(au[mf].y), __float_as_uint(av[mf].y),
                                 bu[nf][0], bu[nf][1]);
            }
        }
        __syncthreads();
        if (kb + 2 < 16) {
            STSA(kb & 1);
            CPB(kb + 2, kb & 1);
            if (kb + 3 < 16) LDGA(kb + 3);
        }
    }

#pragma unroll
    for (int mf = 0; mf < 2; mf++) {
#pragma unroll
        for (int nf = 0; nf < 4; nf++) {
            const int cc = wn * 32 + nf * 8 + 2 * t4;
            const int n  = n0 + cc;
            const int cta = (n & 1023) >> 3;
            const int loc = ((n >> 10) << 3) + (n & 7);
            const float bz0 = bias_s[cc], bz1 = bias_s[cc + 1];
#pragma unroll
            for (int e = 0; e < 2; e++) {
                const int rr = wm * 32 + mf * 16 + gid + e * 8;
                const int b = rr & 63, tt = t0 + (rr >> 6);
                float2 v;
                v.x = C[mf][nf][2 * e]     + bz0;
                v.y = C[mf][nf][2 * e + 1] + bz1;
                *(float2*)&d_gates[(((size_t)tt * NCTA + cta) * BATCH + b) * CPC + loc] = v;
            }
        }
    }
#undef LDGA
#undef STSA
#undef CPB
}

// ================= K3: persistent LSTM recurrence — warp-local pipelines ================
// 512 threads, 16 warps: warp (wm, kq) owns M rows [32wm,32wm+32) x K cols [128kq,128kq+128).
// Each warp stages its own 32x16 h sub-tiles (2-buffer ring, per-warp cp.async groups),
// gated by its own 2 producer flags per chunk. NO CTA-wide sync in the chunk loop.
// SMEM: Ws[32][1032] (132096B) | per-warp rings 16x2x512 floats (65536B) | gs 8x32x34 (34816B)
#define WS_STR 1032
#define TILE_F 512
#define HS_OFF (32 * WS_STR)                  // floats: 33024
#define GS_OFF (HS_OFF + 16 * 2 * TILE_F)     // floats: 49408
#define GS_STR 34
#define K3_SMEM ((GS_OFF + 8 * 32 * GS_STR) * 4)   // 232448 bytes

__global__ __launch_bounds__(512, 1) void k_lstm(const float* __restrict__ whh) {
    extern __shared__ float sm[];
    float* Ws = sm;                 // [32][1032]
    float* hs = sm + HS_OFF;        // 16 warps x 2 bufs x 512 floats
    float* gs = sm + GS_OFF;        // [8][32][34]

    const int tid  = threadIdx.x;
    const int j    = blockIdx.x;
    const int lane = tid & 31, wid = tid >> 5;
    const int gid  = lane >> 2, t4 = lane & 3;
    const int wm   = wid & 1, kq = wid >> 1;   // M-half, K-eighth

    // build Ws[n][perm(k)] = tf32(whh[k][gcol(n)])
    for (int idx = tid; idx < 32 * HID; idx += 512) {
        const int n = idx >> 10, k = idx & 1023;
        const int gcol = ((n >> 3) << 10) + j * HPC + (n & 7);
        Ws[n * WS_STR + (k & ~7) + p8(k & 7)] = tf32r(whh[(size_t)k * G4 + gcol]);
    }
    __syncthreads();

    float* mytile = hs + wid * 2 * TILE_F;
    const uint32_t mysb = smem_u32(mytile);
    const unsigned* Fp = (const unsigned*)d_flags + 16 * kq + (lane & 1);  // lanes 0/1 poll
    const int b0 = tid >> 3, h0 = tid & 7;     // one (batch, hid) pair per thread
    const int gslot = (b0 >> 5) * 4;           // this thread's gs slot group
    const int rb = (b0 & 31) * GS_STR;
    float creg = 0.f;

#define STAGE(BUF, CH) do { \
    uint32_t _d = mysb + (((BUF) * TILE_F) + lane * 16) * 4; \
    const float* _s = rowp + (CH) * 16; \
    cp16_sm(_d,      _s);      cp16_sm(_d + 16, _s + 4); \
    cp16_sm(_d + 32, _s + 8);  cp16_sm(_d + 48, _s + 12); \
    asm volatile("cp.async.commit_group;" ::: "memory"); \
} while (0)

#define SPIN(CH) do { \
    if (lane < 2) { unsigned _v; \
        do { _v = ld_acq(Fp + 2 * (CH)); } while (_v < (unsigned)t); } \
    __syncwarp(); \
} while (0)

    for (int t = 0; t < SEQ; t++) {
        // prefetch this step's input-gate preactivations
        const float* gx = d_gates + (((size_t)t * NCTA + j) * BATCH + b0) * CPC + h0;
        float pg[4];
#pragma unroll
        for (int g = 0; g < 4; g++) pg[g] = gx[g * 8];

        float a[4];
#pragma unroll
        for (int g = 0; g < 4; g++) a[g] = pg[g];

        if (t > 0) {
            const float* rowp = d_hbuf[(t - 1) & 1] + (size_t)(32 * wm + lane) * HID + 128 * kq;
            float Cf[2][4][4] = {};

            SPIN(0); STAGE(0, 0);
            SPIN(1); STAGE(1, 1);
#pragma unroll
            for (int c = 0; c < 8; c++) {
                if (c < 7) asm volatile("cp.async.wait_group 1;" ::: "memory");
                else       asm volatile("cp.async.wait_group 0;" ::: "memory");
                __syncwarp();
                {
                    const float* buf = mytile + (c & 1) * TILE_F;
#pragma unroll
                    for (int ks = 0; ks < 2; ks++) {
                        const int cb = ks * 8 + 2 * t4;
                        float2 au[2], av[2];
#pragma unroll
                        for (int mf = 0; mf < 2; mf++) {
                            const int rl = mf * 16 + gid;
                            au[mf] = *(const float2*)(buf + rl * 16 + cb);
                            av[mf] = *(const float2*)(buf + (rl + 8) * 16 + cb);
                        }
                        uint32_t bu[4][2];
#pragma unroll
                        for (int nf = 0; nf < 4; nf++) {
                            float2 bv = *(const float2*)(Ws + (nf * 8 + gid) * WS_STR
                                                         + kq * 128 + c * 16 + ks * 8 + 2 * t4);
                            bu[nf][0] = __float_as_uint(bv.x);
                            bu[nf][1] = __float_as_uint(bv.y);
                        }
#pragma unroll
                        for (int mf = 0; mf < 2; mf++)
#pragma unroll
                            for (int nf = 0; nf < 4; nf++)
                                mma_tf32(Cf[mf][nf],
                                         __float_as_uint(au[mf].x), __float_as_uint(av[mf].x),
                                         __float_as_uint(au[mf].y), __float_as_uint(av[mf].y),
                                         bu[nf][0], bu[nf][1]);
                    }
                }
                if (c < 6) {
                    SPIN(c + 2);
                    STAGE(c & 1, c + 2);
                }
            }

            // two-phase partial reduction through gs[8 slots]
            const int gbase = (wm * 4 + (kq & 3)) * 32 * GS_STR;
            if (kq < 4) {
#pragma unroll
                for (int mf = 0; mf < 2; mf++) {
                    const int rl = mf * 16 + gid;
#pragma unroll
                    for (int nf = 0; nf < 4; nf++) {
                        float2 w0, w1;
                        w0.x = Cf[mf][nf][0]; w0.y = Cf[mf][nf][1];
                        w1.x = Cf[mf][nf][2]; w1.y = Cf[mf][nf][3];
                        *(float2*)&gs[gbase + rl * GS_STR + nf * 8 + 2 * t4]       = w0;
                        *(float2*)&gs[gbase + (rl + 8) * GS_STR + nf * 8 + 2 * t4] = w1;
                    }
                }
            }
            __syncthreads();
#pragma unroll
            for (int q = 0; q < 4; q++) {
                const int base = (gslot + q) * 32 * GS_STR + rb;
#pragma unroll
                for (int g = 0; g < 4; g++) a[g] += gs[base + g * 8 + h0];
            }
            __syncthreads();
            if (kq >= 4) {
#pragma unroll
                for (int mf = 0; mf < 2; mf++) {
                    const int rl = mf * 16 + gid;
#pragma unroll
                    for (int nf = 0; nf < 4; nf++) {
                        float2 w0, w1;
                        w0.x = Cf[mf][nf][0]; w0.y = Cf[mf][nf][1];
                        w1.x = Cf[mf][nf][2]; w1.y = Cf[mf][nf][3];
                        *(float2*)&gs[gbase + rl * GS_STR + nf * 8 + 2 * t4]       = w0;
                        *(float2*)&gs[gbase + (rl + 8) * GS_STR + nf * 8 + 2 * t4] = w1;
                    }
                }
            }
            __syncthreads();
#pragma unroll
            for (int q = 0; q < 4; q++) {
                const int base = (gslot + q) * 32 * GS_STR + rb;
#pragma unroll
                for (int g = 0; g < 4; g++) a[g] += gs[base + g * 8 + h0];
            }
        }

        // fused LSTM cell: 1 (b,hid) pair per thread
        {
            const float gi = sigf(a[0]), gf = sigf(a[1]), gg = tanf_(a[2]), go = sigf(a[3]);
            creg = gf * creg + gi * gg;
            d_hbuf[t & 1][(size_t)b0 * HID + j * HPC + p8(h0)] = go * tanf_(creg);
        }
        __syncthreads();
        if (tid == 0) {
            asm volatile("fence.acq_rel.gpu;" ::: "memory");
            asm volatile("st.release.gpu.global.u32 [%0], %1;"
                         :: "l"((unsigned*)&d_flags[j]), "r"((unsigned)(t + 1)) : "memory");
        }
    }
#undef STAGE
#undef SPIN
}

// ================= K4: logits (un-permute h) ================
__global__ void k_out(const float* __restrict__ ow, const float* __restrict__ ob,
                      float* __restrict__ out) {
    const int tid = threadIdx.x;
    if (tid >= 128) return;
    const int b = tid >> 1, n = tid & 1;
    const float* h = d_hbuf[1] + (size_t)b * HID;   // step 511 wrote buffer 1
    float acc = ob[n];
    for (int c = 0; c < HID; c++) {
        const int phys = (c & ~7) + p8(c & 7);
        acc += h[phys] * ow[c * 2 + n];
    }
    out[b * 2 + n] = acc;
}

// ================= launch ================
extern "C" void kernel_launch(void* const* d_in, const int* in_sizes, int n_in,
                              void* d_out, int out_size) {
    const int*   x    = (const int*)  d_in[0];
    const float* embT = (const float*)d_in[1];
    const float* bw   = (const float*)d_in[2];
    const float* bb   = (const float*)d_in[3];
    const float* wih  = (const float*)d_in[4];
    const float* whh  = (const float*)d_in[5];
    const float* bih  = (const float*)d_in[6];
    const float* bhh  = (const float*)d_in[7];
    const float* ow   = (const float*)d_in[8];
    const float* ob   = (const float*)d_in[9];
    float*       out  = (float*)d_out;

    cudaFuncSetAttribute(k_gates, cudaFuncAttributeMaxDynamicSharedMemorySize, KG_SMEM);
    cudaFuncSetAttribute(k_lstm,  cudaFuncAttributeMaxDynamicSharedMemorySize, K3_SMEM);

    k_fold<<<dim3(G4 / 64, EMB / 64), 256>>>(bw, wih);
    k_bias<<<dim3(G4 / 256), 256>>>(bb, wih, bih, bhh);
    k_gates<<<dim3(G4 / 64, SEQ / 2), 256, KG_SMEM>>>(x, embT);
    k_lstm<<<NCTA, 512, K3_SMEM>>>(whh);
    k_out<<<1, 128>>>(ow, ob, out);
}

// round 13
// speedup vs baseline: 1.4279x; 1.4279x over previous
#include <cuda_runtime.h>
#include <cuda_bf16.h>
#include <cstdint>

// ---------------- problem constants ----------------
#define SEQ   512
#define BATCH 64
#define EMB   512
#define HID   1024
#define G4    4096
#define NCTA  128
#define HPC   8
#define CPC   32

// ---------------- device scratch ----------------
__device__ float             d_WfoldT[(size_t)G4 * EMB];                // 8 MB, [n][k] transposed+perm
__device__ float             d_bias2[G4];
__device__ float             d_gates[(size_t)SEQ * NCTA * BATCH * CPC]; // 512 MB [t][cta][b][32]
__device__ float             d_hbuf[2][BATCH * HID];                    // k-permuted storage
__device__ volatile unsigned d_flags[NCTA];

// ---------------- helpers ----------------
__device__ __forceinline__ int p8(int e) { return ((e & 3) << 1) | (e >> 2); }

__device__ __forceinline__ float tf32r(float x) {
    uint32_t u;
    asm("cvt.rna.tf32.f32 %0, %1;" : "=r"(u) : "f"(x));
    return __uint_as_float(u);
}
__device__ __forceinline__ float sigf(float x) { return __fdividef(1.f, 1.f + __expf(-x)); }
__device__ __forceinline__ float tanf_(float x) { return __fdividef(2.f, 1.f + __expf(-2.f * x)) - 1.f; }

__device__ __forceinline__ uint32_t smem_u32(const void* p) {
    uint32_t a;
    asm("{ .reg .u64 t; cvta.to.shared.u64 t, %1; cvt.u32.u64 %0, t; }" : "=r"(a) : "l"(p));
    return a;
}
__device__ __forceinline__ void cp16_sm(uint32_t s, const float* g) {
    asm volatile("cp.async.cg.shared.global [%0], [%1], 16;" :: "r"(s), "l"(g));
}
__device__ __forceinline__ void mma_tf32(float c[4],
                                         uint32_t a0, uint32_t a1, uint32_t a2, uint32_t a3,
                                         uint32_t b0, uint32_t b1) {
    asm volatile(
        "mma.sync.aligned.m16n8k8.row.col.f32.tf32.tf32.f32 "
        "{%0,%1,%2,%3}, {%4,%5,%6,%7}, {%8,%9}, {%0,%1,%2,%3};\n"
        : "+f"(c[0]), "+f"(c[1]), "+f"(c[2]), "+f"(c[3])
        : "r"(a0), "r"(a1), "r"(a2), "r"(a3), "r"(b0), "r"(b1));
}

// ================= K1: fold  WfoldT[n][perm(k)] = (bridge_w @ w_ih)[k][n] =================
__global__ __launch_bounds__(256) void k_fold(const float* __restrict__ bw,
                                              const float* __restrict__ wih) {
    __shared__ float As[64][17];
    __shared__ float Bs[16][68];
    const int tid = threadIdx.x;
    const int n0 = blockIdx.x * 64, m0 = blockIdx.y * 64;
    const int tx = tid & 15, ty = tid >> 4;
    const int ar = tid >> 2, ac4 = (tid & 3) * 4;
    const int br = tid >> 4, bc4 = (tid & 15) * 4;

    float acc[4][4] = {};
    for (int kc = 0; kc < 512; kc += 16) {
        float4 av = *(const float4*)(bw + (size_t)(m0 + ar) * 512 + kc + ac4);
        As[ar][ac4 + 0] = av.x; As[ar][ac4 + 1] = av.y;
        As[ar][ac4 + 2] = av.z; As[ar][ac4 + 3] = av.w;
        float4 bv = *(const float4*)(wih + (size_t)(kc + br) * G4 + n0 + bc4);
        Bs[br][bc4 + 0] = bv.x; Bs[br][bc4 + 1] = bv.y;
        Bs[br][bc4 + 2] = bv.z; Bs[br][bc4 + 3] = bv.w;
        __syncthreads();
#pragma unroll
        for (int k = 0; k < 16; k++) {
            float a[4], b[4];
#pragma unroll
            for (int i = 0; i < 4; i++) a[i] = As[ty * 4 + i][k];
#pragma unroll
            for (int j = 0; j < 4; j++) b[j] = Bs[k][tx * 4 + j];
#pragma unroll
            for (int i = 0; i < 4; i++)
#pragma unroll
                for (int j = 0; j < 4; j++) acc[i][j] += a[i] * b[j];
        }
        __syncthreads();
    }
#pragma unroll
    for (int i = 0; i < 4; i++) {
        const int m = m0 + ty * 4 + i;
        const int mp = (m & ~7) | p8(m & 7);
#pragma unroll
        for (int j = 0; j < 4; j++)
            d_WfoldT[(size_t)(n0 + tx * 4 + j) * 512 + mp] = tf32r(acc[i][j]);
    }
}

// ================= Kb: bias2 ; reset flags ================
__global__ __launch_bounds__(256) void k_bias(const float* __restrict__ bb,
                                              const float* __restrict__ wih,
                                              const float* __restrict__ bih,
                                              const float* __restrict__ bhh) {
    const int g = blockIdx.x * blockDim.x + threadIdx.x;
    if (g < NCTA) d_flags[g] = 0u;
    if (g >= G4) return;
    float acc = bih[g] + bhh[g];
    for (int e = 0; e < 512; e++) acc += bb[e] * wih[(size_t)e * G4 + g];
    d_bias2[g] = acc;
}

// ================= K2: gates = gather(emb) @ Wfold + bias2 ================
// M=128 (2 timesteps x 64 batch), N=128, K=512 in 16 chunks of 32.
// 8 warps of 32x64 tiles; cp.async double-buffered B; vectorized LDS via K pair-perm.
#define AS_STR 36
#define KG_SMEM ((2 * 128 * AS_STR + 2 * 128 * AS_STR + 128) * 4)   // 74240 B

__global__ __launch_bounds__(256, 2) void k_gates(const int* __restrict__ x,
                                                  const float* __restrict__ emb) {
    extern __shared__ float sg[];
    float* As = sg;                          // [2][128][36]
    float* Bs = sg + 2 * 128 * AS_STR;       // [2][128][36]
    float* bias_s = Bs + 2 * 128 * AS_STR;   // [128]
    const uint32_t sbB = smem_u32(Bs);

    const int tid  = threadIdx.x;
    const int t0   = blockIdx.y * 2;
    const int n0   = blockIdx.x * 128;
    const int lane = tid & 31, wid = tid >> 5;
    const int gid  = lane >> 2, t4 = lane & 3;
    const int wm   = wid >> 1, wn = wid & 1;   // 4x2 warp grid, warp tile 32x64

    if (tid < 128) bias_s[tid] = d_bias2[n0 + tid];

    const int r    = tid >> 1, half = tid & 1;
    const int tokb = r & 63, tokt = t0 + (r >> 6);
    const float* arow = emb + (size_t)x[(size_t)tokb * SEQ + tokt] * EMB;

    float4 RA[2][2];
#define LDGA(KB) do { \
    const int _e0 = (KB) * 32 + half * 16; \
    RA[0][0] = *(const float4*)(arow + _e0);      RA[0][1] = *(const float4*)(arow + _e0 + 4); \
    RA[1][0] = *(const float4*)(arow + _e0 + 8);  RA[1][1] = *(const float4*)(arow + _e0 + 12); \
} while (0)
#define STSA(BUF) do { \
    float* _dst = As + (BUF) * 128 * AS_STR + r * AS_STR + half * 16; \
    _Pragma("unroll") for (int _g = 0; _g < 2; _g++) { \
        const float* _f0 = (const float*)&RA[_g][0]; \
        const float* _f1 = (const float*)&RA[_g][1]; \
        _Pragma("unroll") for (int _i = 0; _i < 4; _i++) { \
            float2 _pr; _pr.x = tf32r(_f0[_i]); _pr.y = tf32r(_f1[_i]); \
            *(float2*)(_dst + _g * 8 + 2 * _i) = _pr; \
        } \
    } \
} while (0)
#define CPB(KB, BUF) do { \
    _Pragma("unroll") for (int _i = 0; _i < 4; _i++) { \
        const int _idx = tid + _i * 256; \
        const int _n = _idx >> 3, _f = _idx & 7; \
        cp16_sm(sbB + ((BUF) * 128 * AS_STR + _n * AS_STR + _f * 4) * 4, \
                d_WfoldT + (size_t)(n0 + _n) * 512 + (KB) * 32 + _f * 4); \
    } \
    asm volatile("cp.async.commit_group;" ::: "memory"); \
} while (0)

    float C[2][8][4] = {};

    LDGA(0); CPB(0, 0); STSA(0);
    LDGA(1); CPB(1, 1); STSA(1);
    LDGA(2);

    for (int kb = 0; kb < 16; kb++) {
        if (kb < 15) asm volatile("cp.async.wait_group 1;" ::: "memory");
        else         asm volatile("cp.async.wait_group 0;" ::: "memory");
        __syncthreads();
        {
            const float* Ab = As + (kb & 1) * 128 * AS_STR;
            const float* Bb = Bs + (kb & 1) * 128 * AS_STR;
#pragma unroll
            for (int ks = 0; ks < 4; ks++) {
                float2 au[2], av[2];
#pragma unroll
                for (int mf = 0; mf < 2; mf++) {
                    const int rr = wm * 32 + mf * 16 + gid;
                    au[mf] = *(const float2*)(Ab + rr * AS_STR + ks * 8 + 2 * t4);
                    av[mf] = *(const float2*)(Ab + (rr + 8) * AS_STR + ks * 8 + 2 * t4);
                }
                uint32_t bu[8][2];
#pragma unroll
                for (int nf = 0; nf < 8; nf++) {
                    float2 bv = *(const float2*)(Bb + (wn * 64 + nf * 8 + gid) * AS_STR + ks * 8 + 2 * t4);
                    bu[nf][0] = __float_as_uint(bv.x);
                    bu[nf][1] = __float_as_uint(bv.y);
                }
#pragma unroll
                for (int mf = 0; mf < 2; mf++)
#pragma unroll
                    for (int nf = 0; nf < 8; nf++)
                        mma_tf32(C[mf][nf],
                                 __float_as_uint(au[mf].x), __float_as_uint(av[mf].x),
                                 __float_as_uint(au[mf].y), __float_as_uint(av[mf].y),
                                 bu[nf][0], bu[nf][1]);
            }
        }
        __syncthreads();
        if (kb + 2 < 16) {
            STSA(kb & 1);
            CPB(kb + 2, kb & 1);
            if (kb + 3 < 16) LDGA(kb + 3);
        }
    }

    // epilogue: +bias2, permute into [t][cta][b][32]
#pragma unroll
    for (int mf = 0; mf < 2; mf++) {
#pragma unroll
        for (int nf = 0; nf < 8; nf++) {
            const int cc = wn * 64 + nf * 8 + 2 * t4;
            const int n  = n0 + cc;
            const int cta = (n & 1023) >> 3;
            const int loc = ((n >> 10) << 3) + (n & 7);
            const float bz0 = bias_s[cc], bz1 = bias_s[cc + 1];
#pragma unroll
            for (int e = 0; e < 2; e++) {
                const int rr = wm * 32 + mf * 16 + gid + e * 8;
                const int b = rr & 63, tt = t0 + (rr >> 6);
                float2 v;
                v.x = C[mf][nf][2 * e]     + bz0;
                v.y = C[mf][nf][2 * e + 1] + bz1;
                *(float2*)&d_gates[(((size_t)tt * NCTA + cta) * BATCH + b) * CPC + loc] = v;
            }
        }
    }
#undef LDGA
#undef STSA
#undef CPB
}

// ================= K3: persistent LSTM recurrence (EXACT R8 best: 6.96ms) ================
// 512 threads, 16 warps = M-split 2 x K-split 8. Per-chunk producer gating.
// SMEM: Ws[32][1032] (132KB) | overlay region: hs[2][64][132] / gs[16][32][34] (69.6KB)
#define WS_STR 1032
#define HS_STR 132
#define GS_STR 34
#define HS_OFF (32 * WS_STR)
#define HS_BUF (64 * HS_STR)
#define OVL_FLOATS (16 * 32 * GS_STR)    // 17408 > 2*HS_BUF (16896)
#define K3_SMEM ((HS_OFF + OVL_FLOATS) * 4)   // 201728 bytes

__global__ __launch_bounds__(512, 1) void k_lstm(const float* __restrict__ whh) {
    extern __shared__ float sm[];
    float* Ws = sm;                 // [32][1032]
    float* hs = sm + HS_OFF;        // [2][64][132]
    float* gs = hs;                 // overlay [16][32][34]
    const uint32_t sbH = smem_u32(hs);

    const int tid  = threadIdx.x;
    const int j    = blockIdx.x;
    const int lane = tid & 31, wid = tid >> 5;
    const int gid  = lane >> 2, t4 = lane & 3;
    const int wm   = wid & 1, kq = wid >> 1;   // M-half, K-eighth

    // build Ws[n][perm(k)] = tf32(whh[k][gcol(n)])
    for (int idx = tid; idx < 32 * HID; idx += 512) {
        const int n = idx >> 10, k = idx & 1023;
        const int gcol = ((n >> 3) << 10) + j * HPC + (n & 7);
        Ws[n * WS_STR + (k & ~7) + p8(k & 7)] = tf32r(whh[(size_t)k * G4 + gcol]);
    }
    __syncthreads();

    const int b0 = tid >> 3, h0 = tid & 7;   // one (batch, hid) pair per thread
    const int pfj = tid & 15;                // flag index within a chunk's producer set
    float creg = 0.f;

#define STAGE(BUF, CH, HP) do { \
    _Pragma("unroll") for (int _i = 0; _i < 4; _i++) { \
        const int _idx = tid + _i * 512; \
        const int _r = _idx >> 5, _f = _idx & 31; \
        cp16_sm(sbH + ((BUF) * HS_BUF + _r * HS_STR + _f * 4) * 4, \
                (HP) + (size_t)_r * HID + (CH) * 128 + _f * 4); \
    } \
    asm volatile("cp.async.commit_group;" ::: "memory"); \
} while (0)

// all threads poll one of the 16 producer flags for chunk CH, acquire, then stage
#define GATE_STAGE(BUF, CH, HP) do { \
    const unsigned* _fp = (const unsigned*)d_flags + (CH) * 16 + pfj; \
    unsigned _v; \
    do { asm volatile("ld.acquire.gpu.global.u32 %0, [%1];" : "=r"(_v) : "l"(_fp)); } \
    while (_v < (unsigned)t); \
    STAGE(BUF, CH, HP); \
} while (0)

    for (int t = 0; t < SEQ; t++) {
        // prefetch this step's input-gate preactivations (4 per thread, overlaps polling)
        const float* gx = d_gates + (((size_t)t * NCTA + j) * BATCH + b0) * CPC + h0;
        float pg[4];
#pragma unroll
        for (int g = 0; g < 4; g++) pg[g] = gx[g * 8];

        float Cf[2][4][4] = {};
        if (t > 0) {
            const float* hp = d_hbuf[(t - 1) & 1];

            GATE_STAGE(0, 0, hp);
            GATE_STAGE(1, 1, hp);
#pragma unroll
            for (int c = 0; c < 8; c++) {
                if (c < 7) asm volatile("cp.async.wait_group 1;" ::: "memory");
                else       asm volatile("cp.async.wait_group 0;" ::: "memory");
                __syncthreads();
                {
                    const float* buf = hs + (c & 1) * HS_BUF;
                    const int kb = kq * 16;
#pragma unroll
                    for (int ks = 0; ks < 2; ks++) {
                        const int cb = kb + ks * 8;
                        float2 au[2], av[2];
#pragma unroll
                        for (int mf = 0; mf < 2; mf++) {
                            const int rr = wm * 32 + mf * 16 + gid;
                            au[mf] = *(const float2*)(buf + rr * HS_STR + cb + 2 * t4);
                            av[mf] = *(const float2*)(buf + (rr + 8) * HS_STR + cb + 2 * t4);
                        }
                        uint32_t bu[4][2];
#pragma unroll
                        for (int nf = 0; nf < 4; nf++) {
                            float2 bv = *(const float2*)(Ws + (nf * 8 + gid) * WS_STR + c * 128 + cb + 2 * t4);
                            bu[nf][0] = __float_as_uint(bv.x);
                            bu[nf][1] = __float_as_uint(bv.y);
                        }
#pragma unroll
                        for (int mf = 0; mf < 2; mf++)
#pragma unroll
                            for (int nf = 0; nf < 4; nf++)
                                mma_tf32(Cf[mf][nf],
                                         __float_as_uint(au[mf].x), __float_as_uint(av[mf].x),
                                         __float_as_uint(au[mf].y), __float_as_uint(av[mf].y),
                                         bu[nf][0], bu[nf][1]);
                    }
                }
                __syncthreads();
                if (c + 2 < 8) GATE_STAGE(c & 1, c + 2, hp);
            }

            // stash partial C to gs[(wm*8+kq)][32][34]
            const int gbase = (wm * 8 + kq) * 32 * GS_STR;
#pragma unroll
            for (int mf = 0; mf < 2; mf++) {
                const int rl = mf * 16 + gid;
#pragma unroll
                for (int nf = 0; nf < 4; nf++) {
                    float2 v0, v1;
                    v0.x = Cf[mf][nf][0]; v0.y = Cf[mf][nf][1];
                    v1.x = Cf[mf][nf][2]; v1.y = Cf[mf][nf][3];
                    *(float2*)&gs[gbase + rl * GS_STR + nf * 8 + 2 * t4]       = v0;
                    *(float2*)&gs[gbase + (rl + 8) * GS_STR + nf * 8 + 2 * t4] = v1;
                }
            }
            __syncthreads();
        }

        // fused LSTM cell: 1 (b,hid) pair per thread; reduce 8 K-slice partials
        float a[4];
#pragma unroll
        for (int g = 0; g < 4; g++) a[g] = pg[g];
        if (t > 0) {
            const int wb = (b0 >> 5) * 8;
            const int rb = (b0 & 31) * GS_STR;
#pragma unroll
            for (int q = 0; q < 8; q++) {
                const int base = (wb + q) * 32 * GS_STR + rb;
#pragma unroll
                for (int g = 0; g < 4; g++) a[g] += gs[base + g * 8 + h0];
            }
        }
        {
            const float gi = sigf(a[0]), gf = sigf(a[1]), gg = tanf_(a[2]), go = sigf(a[3]);
            creg = gf * creg + gi * gg;
            d_hbuf[t & 1][(size_t)b0 * HID + j * HPC + p8(h0)] = go * tanf_(creg);
        }
        __syncthreads();
        if (tid == 0) {
            asm volatile("fence.acq_rel.gpu;" ::: "memory");
            asm volatile("st.release.gpu.global.u32 [%0], %1;"
                         :: "l"((unsigned*)&d_flags[j]), "r"((unsigned)(t + 1)) : "memory");
        }
    }
#undef STAGE
#undef GATE_STAGE
}

// ================= K4: logits (un-permute h); 128 blocks, warp-reduce ================
__global__ void k_out(const float* __restrict__ ow, const float* __restrict__ ob,
                      float* __restrict__ out) {
    const int o = blockIdx.x;            // 0..127 = b*2 + n
    const int b = o >> 1, n = o & 1;
    const int tid = threadIdx.x;         // 128 threads
    const float* h = d_hbuf[1] + (size_t)b * HID;   // step 511 wrote buffer 1
    float acc = 0.f;
#pragma unroll
    for (int i = 0; i < 8; i++) {
        const int c = tid + i * 128;
        const int phys = (c & ~7) + p8(c & 7);
        acc += h[phys] * ow[c * 2 + n];
    }
    __shared__ float red[4];
#pragma unroll
    for (int s = 16; s > 0; s >>= 1) acc += __shfl_down_sync(0xffffffffu, acc, s);
    if ((tid & 31) == 0) red[tid >> 5] = acc;
    __syncthreads();
    if (tid == 0) out[o] = red[0] + red[1] + red[2] + red[3] + ob[n];
}

// ================= launch ================
extern "C" void kernel_launch(void* const* d_in, const int* in_sizes, int n_in,
                              void* d_out, int out_size) {
    const int*   x    = (const int*)  d_in[0];
    const float* embT = (const float*)d_in[1];
    const float* bw   = (const float*)d_in[2];
    const float* bb   = (const float*)d_in[3];
    const float* wih  = (const float*)d_in[4];
    const float* whh  = (const float*)d_in[5];
    const float* bih  = (const float*)d_in[6];
    const float* bhh  = (const float*)d_in[7];
    const float* ow   = (const float*)d_in[8];
    const float* ob   = (const float*)d_in[9];
    float*       out  = (float*)d_out;

    cudaFuncSetAttribute(k_gates, cudaFuncAttributeMaxDynamicSharedMemorySize, KG_SMEM);
    cudaFuncSetAttribute(k_lstm,  cudaFuncAttributeMaxDynamicSharedMemorySize, K3_SMEM);

    k_fold<<<dim3(G4 / 64, EMB / 64), 256>>>(bw, wih);
    k_bias<<<dim3(G4 / 256), 256>>>(bb, wih, bih, bhh);
    k_gates<<<dim3(G4 / 128, SEQ / 2), 256, KG_SMEM>>>(x, embT);
    k_lstm<<<NCTA, 512, K3_SMEM>>>(whh);
    k_out<<<128, 128>>>(ow, ob, out);
}